// round 4
// baseline (speedup 1.0000x reference)
#include <cuda_runtime.h>

// Problem constants
#define BN    4096
#define NFEAT 1024
#define RR    64
#define KK    32
#define DD    16

// Tiling
#define BT      8     // b rows per block
#define RG      16    // regions per block
#define THREADS 512   // RG regions x KK k-values; warp = one region

#define XPITCH 1028   // smem pitch for raw x rows
#define GPITCH 132    // smem pitch per region for gathered tile [d][b] (16B-aligned)

#define LOG_2PI_F 1.8378770664093453f

typedef unsigned long long u64;

// Packed fp32x2 helpers (sm_103a FFMA2 path — only reachable via PTX)
__device__ __forceinline__ u64 ffma2(u64 a, u64 b, u64 c) {
    u64 d;
    asm("fma.rn.f32x2 %0, %1, %2, %3;" : "=l"(d) : "l"(a), "l"(b), "l"(c));
    return d;
}
__device__ __forceinline__ u64 bcast2(float v) {
    u64 d;
    unsigned int r = __float_as_uint(v);
    asm("mov.b64 %0, {%1, %1};" : "=l"(d) : "r"(r));
    return d;
}
__device__ __forceinline__ void unpack2(u64 v, float& lo, float& hi) {
    unsigned int a, b;
    asm("mov.b64 {%0, %1}, %2;" : "=r"(a), "=r"(b) : "l"(v));
    lo = __uint_as_float(a);
    hi = __uint_as_float(b);
}

// Precomputed parameters (device globals: no allocation allowed)
__device__ float g_wa[RR * KK * DD];   // [r][k][d] = 1/scale
__device__ float g_wb[RR * KK * DD];   // [r][k][d] = -mean/scale
__device__ float g_c [RR * KK];        // [r][k]    = -sum_d log(scale) - 0.5*D*log(2pi)
__device__ int   g_idx[RR * DD];       // region indices as int32

// ---------------------------------------------------------------------------
// Prep kernel: 64 blocks (one per region) x 512 threads.
// ---------------------------------------------------------------------------
__global__ void prep_kernel(const float* __restrict__ means,
                            const float* __restrict__ scales,
                            const void*  __restrict__ regions_raw) {
    const int r = blockIdx.x;
    const int t = threadIdx.x;       // 0..511
    const int k = t >> 4;
    const int d = t & 15;

    const size_t idx = ((size_t)r * KK + k) * DD + d;
    const float s   = scales[idx];
    const float m   = means [idx];
    const float inv = 1.0f / s;
    g_wa[idx] = inv;          // [r][k][d] layout: thread slice is contiguous
    g_wb[idx] = -m * inv;

    float lg = logf(s);
#pragma unroll
    for (int o = 8; o >= 1; o >>= 1)
        lg += __shfl_xor_sync(0xffffffffu, lg, o);
    if (d == 0)
        g_c[r * KK + k] = -lg - 0.5f * (float)DD * LOG_2PI_F;

    if (r == 0) {
        // int64 detection: if regions is int64 (values < 1024), every odd
        // 32-bit word is zero.
        __shared__ int s_or;
        if (t == 0) s_or = 0;
        __syncthreads();
        const int* w = (const int*)regions_raw;
        int v = w[2 * t + 1];
#pragma unroll
        for (int o = 16; o >= 1; o >>= 1)
            v |= __shfl_xor_sync(0xffffffffu, v, o);
        if ((t & 31) == 0) atomicOr(&s_or, v);
        __syncthreads();
        const int is64 = (s_or == 0);
        g_idx[2 * t]     = is64 ? w[4 * t]     : w[2 * t];
        g_idx[2 * t + 1] = is64 ? w[4 * t + 2] : w[2 * t + 1];
    }
}

// ---------------------------------------------------------------------------
// Main kernel: block = (BT=8 b-rows) x (RG=16 regions), 512 threads.
// Thread (rl = tid>>5, k = tid&31) computes an 8b x 1k tile.
//  - warp == one region: phase-3 LDS.128 are warp-uniform broadcasts
//  - ALL 16-d weights (32 floats) live in registers, loaded once
//  - accumulators packed over b-pairs -> FFMA2 throughout
// ---------------------------------------------------------------------------
__global__ __launch_bounds__(THREADS, 2)
void main_kernel(const float* __restrict__ x, float* __restrict__ out) {
    __shared__ float sm_x [BT * XPITCH];   // 32,896 B
    __shared__ float sm_xg[RG * GPITCH];   //  8,448 B

    const int tid = threadIdx.x;
    const int b0  = blockIdx.x * BT;
    const int r0  = blockIdx.y * RG;

    const int rl = tid >> 5;         // region within block: 0..15  (warp id)
    const int k  = tid & 31;         // k value: lane id
    const int r  = r0 + rl;

    // ---- Preload full weight slice into registers (contiguous float4s) ----
    float wa[DD], wb[DD];
    {
        const float4* wap = (const float4*)&g_wa[((size_t)r * KK + k) * DD];
        const float4* wbp = (const float4*)&g_wb[((size_t)r * KK + k) * DD];
#pragma unroll
        for (int j = 0; j < DD / 4; j++) {
            ((float4*)wa)[j] = wap[j];
            ((float4*)wb)[j] = wbp[j];
        }
    }

    // ---- Phase 1: load BT rows of x, fully coalesced float4 ----
    {
        const float4* xs = (const float4*)(x + (size_t)b0 * NFEAT);
#pragma unroll
        for (int i = tid; i < BT * (NFEAT / 4); i += THREADS) {
            const int row = i >> 8;     // NFEAT/4 == 256
            const int c   = i & 255;
            *(float4*)&sm_x[row * XPITCH + c * 4] = xs[row * 256 + c];
        }
    }
    __syncthreads();

    // ---- Phase 2: gather into sm_xg[rl][d*BT + b] ----
#pragma unroll
    for (int j = 0; j < 4; j++) {
        const int e  = tid + j * THREADS;
        const int b  = e & (BT - 1);
        const int d  = (e >> 3) & (DD - 1);
        const int rg = e >> 7;
        const int col = g_idx[(r0 + rg) * DD + d];
        sm_xg[rg * GPITCH + d * BT + b] = sm_x[b * XPITCH + col];
    }
    __syncthreads();

    // ---- Phase 3: packed compute; per d: 2 LDS.128 + 2 mov + 8 FFMA2 ----
    const float* xp = sm_xg + rl * GPITCH;

    u64 acc[4];
#pragma unroll
    for (int p = 0; p < 4; p++) acc[p] = 0ull;

#pragma unroll
    for (int d = 0; d < DD; d++) {
        const ulonglong2 xA = *(const ulonglong2*)(xp + d * BT);      // b0..3
        const ulonglong2 xB = *(const ulonglong2*)(xp + d * BT + 4);  // b4..7
        const u64 aa = bcast2(wa[d]);
        const u64 bb = bcast2(wb[d]);
        u64 z;
        z = ffma2(xA.x, aa, bb); acc[0] = ffma2(z, z, acc[0]);
        z = ffma2(xA.y, aa, bb); acc[1] = ffma2(z, z, acc[1]);
        z = ffma2(xB.x, aa, bb); acc[2] = ffma2(z, z, acc[2]);
        z = ffma2(xB.y, aa, bb); acc[3] = ffma2(z, z, acc[3]);
    }

    // ---- Epilogue: out[b][r][k] = -0.5*acc + C, coalesced over lanes ----
    const u64 nh = bcast2(-0.5f);
    const u64 cc = bcast2(g_c[r * KK + k]);
#pragma unroll
    for (int p = 0; p < 4; p++) {
        const u64 o = ffma2(acc[p], nh, cc);
        float lo, hi;
        unpack2(o, lo, hi);
        out[((size_t)(b0 + 2 * p)     * RR + r) * KK + k] = lo;
        out[((size_t)(b0 + 2 * p + 1) * RR + r) * KK + k] = hi;
    }
}

// ---------------------------------------------------------------------------
extern "C" void kernel_launch(void* const* d_in, const int* in_sizes, int n_in,
                              void* d_out, int out_size) {
    const float* x       = (const float*)d_in[0];
    const void*  regions = d_in[1];                // int64 or int32, detected
    const float* means   = (const float*)d_in[2];
    const float* scales  = (const float*)d_in[3];
    float*       out     = (float*)d_out;

    prep_kernel<<<RR, 512>>>(means, scales, regions);

    dim3 grid(BN / BT, RR / RG);
    main_kernel<<<grid, THREADS>>>(x, out);
}

// round 5
// speedup vs baseline: 1.5055x; 1.5055x over previous
#include <cuda_runtime.h>

// Problem constants
#define BN    4096
#define NFEAT 1024
#define RR    64
#define KK    32
#define DD    16

// Tiling
#define BT      8     // b rows per block
#define RG      16    // regions per block
#define THREADS 256

#define XPITCH 1028   // smem pitch for raw x rows (bank-decorrelated gather)
#define GPITCH 132    // smem pitch per region for gathered tile [d][b]

#define LOG_2PI_F 1.8378770664093453f

typedef unsigned long long u64;

// Packed fp32x2 helpers (sm_103a FFMA2 path — only reachable via PTX)
__device__ __forceinline__ u64 ffma2(u64 a, u64 b, u64 c) {
    u64 d;
    asm("fma.rn.f32x2 %0, %1, %2, %3;" : "=l"(d) : "l"(a), "l"(b), "l"(c));
    return d;
}
__device__ __forceinline__ u64 bcast2(float v) {
    u64 d;
    unsigned int r = __float_as_uint(v);
    asm("mov.b64 %0, {%1, %1};" : "=l"(d) : "r"(r));
    return d;
}
__device__ __forceinline__ void unpack2(u64 v, float& lo, float& hi) {
    unsigned int a, b;
    asm("mov.b64 {%0, %1}, %2;" : "=r"(a), "=r"(b) : "l"(v));
    lo = __uint_as_float(a);
    hi = __uint_as_float(b);
}
__device__ __forceinline__ unsigned int smem_u32(const void* p) {
    unsigned int a;
    asm("{ .reg .u64 t; cvta.to.shared.u64 t, %1; cvt.u32.u64 %0, t; }"
        : "=r"(a) : "l"(p));
    return a;
}

// Precomputed parameters (device globals: no allocation allowed)
__device__ float g_wa[RR * DD * KK];   // [r][d][k] = 1/scale
__device__ float g_wb[RR * DD * KK];   // [r][d][k] = -mean/scale
__device__ float g_c [RR * KK];        // [r][k]
__device__ int   g_idx[RR * DD];       // region indices as int32

// ---------------------------------------------------------------------------
// Prep kernel: 64 blocks (one per region) x 512 threads.
// ---------------------------------------------------------------------------
__global__ void prep_kernel(const float* __restrict__ means,
                            const float* __restrict__ scales,
                            const void*  __restrict__ regions_raw) {
    const int r = blockIdx.x;
    const int t = threadIdx.x;       // 0..511
    const int k = t >> 4;
    const int d = t & 15;

    const float s   = scales[((size_t)r * KK + k) * DD + d];
    const float m   = means [((size_t)r * KK + k) * DD + d];
    const float inv = 1.0f / s;
    g_wa[(r * DD + d) * KK + k] = inv;
    g_wb[(r * DD + d) * KK + k] = -m * inv;

    float lg = logf(s);
#pragma unroll
    for (int o = 8; o >= 1; o >>= 1)
        lg += __shfl_xor_sync(0xffffffffu, lg, o);
    if (d == 0)
        g_c[r * KK + k] = -lg - 0.5f * (float)DD * LOG_2PI_F;

    if (r == 0) {
        // int64 detection: if regions is int64 (values < 1024), every odd
        // 32-bit word is zero.
        __shared__ int s_or;
        if (t == 0) s_or = 0;
        __syncthreads();
        const int* w = (const int*)regions_raw;
        int v = w[2 * t + 1];
#pragma unroll
        for (int o = 16; o >= 1; o >>= 1)
            v |= __shfl_xor_sync(0xffffffffu, v, o);
        if ((t & 31) == 0) atomicOr(&s_or, v);
        __syncthreads();
        const int is64 = (s_or == 0);
        g_idx[2 * t]     = is64 ? w[4 * t]     : w[2 * t];
        g_idx[2 * t + 1] = is64 ? w[4 * t + 2] : w[2 * t + 1];
    }
}

// ---------------------------------------------------------------------------
// Main kernel: block = (BT=8 b-rows) x (RG=16 regions), 256 threads.
// Thread (rl = tid>>4, kp = tid&15) computes an 8b x 2k tile.
//  - phase 1 via cp.async (no staging registers)
//  - weights loaded in 4d quarters (16 floats live) -> regs <= 64, 4 blk/SM
//  - packed FFMA2 compute throughout
// ---------------------------------------------------------------------------
__global__ __launch_bounds__(THREADS, 4)
void main_kernel(const float* __restrict__ x, float* __restrict__ out) {
    __shared__ float sm_x [BT * XPITCH];   // 32,896 B
    __shared__ float sm_xg[RG * GPITCH];   //  8,448 B

    const int tid = threadIdx.x;
    const int b0  = blockIdx.x * BT;
    const int r0  = blockIdx.y * RG;

    const int rl = tid >> 4;         // region within block: 0..15
    const int kp = tid & 15;         // k-pair index: k0 = kp*2
    const int r  = r0 + rl;
    const int k0 = kp * 2;

    // ---- Phase 1: cp.async BT rows of x into smem, fully coalesced 16B ----
    {
        const unsigned int s_x = smem_u32(sm_x);
        const float* xrow = x + (size_t)b0 * NFEAT;
#pragma unroll
        for (int i = tid; i < BT * (NFEAT / 4); i += THREADS) {
            const int row = i >> 8;     // NFEAT/4 == 256
            const int c   = i & 255;
            const unsigned int dst = s_x + (row * XPITCH + c * 4) * 4;
            const float* src = xrow + (size_t)row * NFEAT + c * 4;
            asm volatile("cp.async.cg.shared.global [%0], [%1], 16;"
                         :: "r"(dst), "l"(src));
        }
        asm volatile("cp.async.commit_group;\n\tcp.async.wait_group 0;" ::: "memory");
    }
    __syncthreads();

    // ---- Phase 2: gather into sm_xg[rl][d*BT + b] ----
#pragma unroll
    for (int j = 0; j < 8; j++) {
        const int e  = tid + j * THREADS;
        const int b  = e & (BT - 1);
        const int d  = (e >> 3) & (DD - 1);
        const int rg = e >> 7;
        const int col = g_idx[(r0 + rg) * DD + d];
        sm_xg[rg * GPITCH + d * BT + b] = sm_x[b * XPITCH + col];
    }
    __syncthreads();

    // ---- Phase 3: packed compute, weights in 4d quarters ----
    const float* xp = sm_xg + rl * GPITCH;
    const float* wap = g_wa + r * DD * KK + k0;
    const float* wbp = g_wb + r * DD * KK + k0;

    u64 acc0[4], acc1[4];
#pragma unroll
    for (int p = 0; p < 4; p++) { acc0[p] = 0ull; acc1[p] = 0ull; }

#pragma unroll 1
    for (int q = 0; q < 4; q++) {
        float2 wa2[4], wb2[4];
        const int dbase = q * 4;
#pragma unroll
        for (int d = 0; d < 4; d++) {
            wa2[d] = *(const float2*)(wap + (dbase + d) * KK);
            wb2[d] = *(const float2*)(wbp + (dbase + d) * KK);
        }

#pragma unroll
        for (int d = 0; d < 4; d++) {
            const ulonglong2 xA = *(const ulonglong2*)(xp + (dbase + d) * BT);
            const ulonglong2 xB = *(const ulonglong2*)(xp + (dbase + d) * BT + 4);
            const u64 xv[4] = {xA.x, xA.y, xB.x, xB.y};

            const u64 aa0 = bcast2(wa2[d].x);
            const u64 aa1 = bcast2(wa2[d].y);
            const u64 bb0 = bcast2(wb2[d].x);
            const u64 bb1 = bcast2(wb2[d].y);
#pragma unroll
            for (int p = 0; p < 4; p++) {
                const u64 z0 = ffma2(xv[p], aa0, bb0);
                acc0[p] = ffma2(z0, z0, acc0[p]);
                const u64 z1 = ffma2(xv[p], aa1, bb1);
                acc1[p] = ffma2(z1, z1, acc1[p]);
            }
        }
    }

    // ---- Epilogue: out[b][r][k0..k0+1] = -0.5*acc + C ----
    const float2 c2 = *(const float2*)&g_c[r * KK + k0];
    const u64 nh  = bcast2(-0.5f);
    const u64 cc0 = bcast2(c2.x);
    const u64 cc1 = bcast2(c2.y);
#pragma unroll
    for (int p = 0; p < 4; p++) {
        const u64 o0 = ffma2(acc0[p], nh, cc0);  // k0 for b=2p, 2p+1
        const u64 o1 = ffma2(acc1[p], nh, cc1);  // k1 for b=2p, 2p+1
        float o0lo, o0hi, o1lo, o1hi;
        unpack2(o0, o0lo, o0hi);
        unpack2(o1, o1lo, o1hi);
        float2 s0 = make_float2(o0lo, o1lo);
        float2 s1 = make_float2(o0hi, o1hi);
        *(float2*)&out[((size_t)(b0 + 2 * p)     * RR + r) * KK + k0] = s0;
        *(float2*)&out[((size_t)(b0 + 2 * p + 1) * RR + r) * KK + k0] = s1;
    }
}

// ---------------------------------------------------------------------------
extern "C" void kernel_launch(void* const* d_in, const int* in_sizes, int n_in,
                              void* d_out, int out_size) {
    const float* x       = (const float*)d_in[0];
    const void*  regions = d_in[1];                // int64 or int32, detected
    const float* means   = (const float*)d_in[2];
    const float* scales  = (const float*)d_in[3];
    float*       out     = (float*)d_out;

    prep_kernel<<<RR, 512>>>(means, scales, regions);

    dim3 grid(BN / BT, RR / RG);
    main_kernel<<<grid, THREADS>>>(x, out);
}

// round 6
// speedup vs baseline: 1.5430x; 1.0249x over previous
#include <cuda_runtime.h>

// Problem constants
#define BN    4096
#define NFEAT 1024
#define RR    64
#define KK    32
#define DD    16

// Tiling
#define BT      8     // b rows per tile
#define RG      16    // regions per block
#define THREADS 256
#define GRIDX   74    // persistent blocks per r-group (148 SMs x 2 / 4 groups)
#define NTILES  (BN / BT)   // 512 b-tiles per r-group

#define XPITCH 1028   // smem pitch for raw x rows (bank-decorrelated gather)
#define GPITCH 132    // smem pitch per region for gathered tile [d][b]

#define LOG_2PI_F 1.8378770664093453f

typedef unsigned long long u64;

// Packed fp32x2 helpers (sm_103a FFMA2 — only reachable via PTX)
__device__ __forceinline__ u64 ffma2(u64 a, u64 b, u64 c) {
    u64 d;
    asm("fma.rn.f32x2 %0, %1, %2, %3;" : "=l"(d) : "l"(a), "l"(b), "l"(c));
    return d;
}
__device__ __forceinline__ u64 bcast2(float v) {
    u64 d;
    unsigned int r = __float_as_uint(v);
    asm("mov.b64 %0, {%1, %1};" : "=l"(d) : "r"(r));
    return d;
}
__device__ __forceinline__ void unpack2(u64 v, float& lo, float& hi) {
    unsigned int a, b;
    asm("mov.b64 {%0, %1}, %2;" : "=r"(a), "=r"(b) : "l"(v));
    lo = __uint_as_float(a);
    hi = __uint_as_float(b);
}
__device__ __forceinline__ unsigned int smem_u32(const void* p) {
    unsigned int a;
    asm("{ .reg .u64 t; cvta.to.shared.u64 t, %1; cvt.u32.u64 %0, t; }"
        : "=r"(a) : "l"(p));
    return a;
}

// Precomputed parameters (device globals: no allocation allowed)
__device__ float g_wa[RR * DD * KK];   // [r][d][k] = 1/scale
__device__ float g_wb[RR * DD * KK];   // [r][d][k] = -mean/scale
__device__ float g_c [RR * KK];        // [r][k]
__device__ int   g_idx[RR * DD];       // region indices as int32

// ---------------------------------------------------------------------------
// Prep kernel: 64 blocks (one per region) x 512 threads.
// ---------------------------------------------------------------------------
__global__ void prep_kernel(const float* __restrict__ means,
                            const float* __restrict__ scales,
                            const void*  __restrict__ regions_raw) {
    const int r = blockIdx.x;
    const int t = threadIdx.x;       // 0..511
    const int k = t >> 4;
    const int d = t & 15;

    const float s   = scales[((size_t)r * KK + k) * DD + d];
    const float m   = means [((size_t)r * KK + k) * DD + d];
    const float inv = 1.0f / s;
    g_wa[(r * DD + d) * KK + k] = inv;
    g_wb[(r * DD + d) * KK + k] = -m * inv;

    float lg = logf(s);
#pragma unroll
    for (int o = 8; o >= 1; o >>= 1)
        lg += __shfl_xor_sync(0xffffffffu, lg, o);
    if (d == 0)
        g_c[r * KK + k] = -lg - 0.5f * (float)DD * LOG_2PI_F;

    if (r == 0) {
        // int64 detection: if regions is int64 (values < 1024), every odd
        // 32-bit word is zero.
        __shared__ int s_or;
        if (t == 0) s_or = 0;
        __syncthreads();
        const int* w = (const int*)regions_raw;
        int v = w[2 * t + 1];
#pragma unroll
        for (int o = 16; o >= 1; o >>= 1)
            v |= __shfl_xor_sync(0xffffffffu, v, o);
        if ((t & 31) == 0) atomicOr(&s_or, v);
        __syncthreads();
        const int is64 = (s_or == 0);
        g_idx[2 * t]     = is64 ? w[4 * t]     : w[2 * t];
        g_idx[2 * t + 1] = is64 ? w[4 * t + 2] : w[2 * t + 1];
    }
}

// ---------------------------------------------------------------------------
// Main kernel: persistent blocks. grid = (74, 4).
// Block (bx, g): r-group g (16 regions), iterates b-tiles t = bx + j*74.
//  - weights (all 16 d) + gather indices loaded ONCE per block
//  - double-buffered cp.async pipeline over b-tiles
//  - thread (rl = tid>>4, kp = tid&15): 8b x 2k tile, packed FFMA2
// ---------------------------------------------------------------------------
__global__ __launch_bounds__(THREADS, 2)
void main_kernel(const float* __restrict__ x, float* __restrict__ out) {
    extern __shared__ float smem[];
    float* sm_x0  = smem;                       // BT*XPITCH
    float* sm_x1  = smem + BT * XPITCH;         // BT*XPITCH
    float* sm_xg  = smem + 2 * BT * XPITCH;     // RG*GPITCH
    int*   sm_idx = (int*)(sm_xg + RG * GPITCH); // RG*DD = 256

    const int tid = threadIdx.x;
    const int r0  = blockIdx.y * RG;

    const int rl = tid >> 4;         // region within block: 0..15
    const int kp = tid & 15;         // k-pair index: k0 = kp*2
    const int r  = r0 + rl;
    const int k0 = kp * 2;

    // ---- One-time: gather indices to smem; weights to registers ----
    sm_idx[tid] = g_idx[r0 * DD + tid];          // 256 == RG*DD

    float2 wa2[DD], wb2[DD];
    {
        const float* wap = g_wa + r * DD * KK + k0;
        const float* wbp = g_wb + r * DD * KK + k0;
#pragma unroll
        for (int d = 0; d < DD; d++) {
            wa2[d] = *(const float2*)(wap + d * KK);
            wb2[d] = *(const float2*)(wbp + d * KK);
        }
    }
    const float2 c2 = *(const float2*)&g_c[r * KK + k0];

    const unsigned int s_x0 = smem_u32(sm_x0);
    const unsigned int s_x1 = smem_u32(sm_x1);

    // ---- Prologue: issue load of first tile into buf0 ----
    const int t0 = blockIdx.x;
    {
        const float* xrow = x + (size_t)t0 * BT * NFEAT;
#pragma unroll
        for (int i = tid; i < BT * (NFEAT / 4); i += THREADS) {
            const int row = i >> 8;
            const int c   = i & 255;
            const unsigned int dst = s_x0 + (unsigned)(row * XPITCH + c * 4) * 4u;
            asm volatile("cp.async.cg.shared.global [%0], [%1], 16;"
                         :: "r"(dst), "l"(xrow + (size_t)row * NFEAT + c * 4));
        }
        asm volatile("cp.async.commit_group;" ::: "memory");
    }

    // ---- Pipelined tile loop ----
    for (int j = 0, t = t0; t < NTILES; j++, t += GRIDX) {
        const int tn = t + GRIDX;
        const unsigned int s_cur = (j & 1) ? s_x1 : s_x0;
        const float* sm_cur      = (j & 1) ? sm_x1 : sm_x0;
        const unsigned int s_nxt = (j & 1) ? s_x0 : s_x1;

        if (tn < NTILES) {
            // Issue next tile's load into the other buffer (safe: all warps
            // passed the barrier ending the gather that last read it).
            const float* xrow = x + (size_t)tn * BT * NFEAT;
#pragma unroll
            for (int i = tid; i < BT * (NFEAT / 4); i += THREADS) {
                const int row = i >> 8;
                const int c   = i & 255;
                const unsigned int dst = s_nxt + (unsigned)(row * XPITCH + c * 4) * 4u;
                asm volatile("cp.async.cg.shared.global [%0], [%1], 16;"
                             :: "r"(dst), "l"(xrow + (size_t)row * NFEAT + c * 4));
            }
            asm volatile("cp.async.commit_group;" ::: "memory");
            asm volatile("cp.async.wait_group 1;" ::: "memory");  // tile t done
        } else {
            asm volatile("cp.async.wait_group 0;" ::: "memory");
        }
        __syncthreads();

        // ---- Gather current tile into sm_xg[rg][d*BT + b] ----
#pragma unroll
        for (int jj = 0; jj < 8; jj++) {
            const int e  = tid + jj * THREADS;
            const int b  = e & (BT - 1);
            const int d  = (e >> 3) & (DD - 1);
            const int rg = e >> 7;
            const int col = sm_idx[rg * DD + d];
            sm_xg[rg * GPITCH + d * BT + b] = sm_cur[b * XPITCH + col];
        }
        __syncthreads();

        // ---- Compute: per d, 2 LDS.128 (broadcast) + 4 mov + 16 FFMA2 ----
        const float* xp = sm_xg + rl * GPITCH;

        u64 acc0[4], acc1[4];
#pragma unroll
        for (int p = 0; p < 4; p++) { acc0[p] = 0ull; acc1[p] = 0ull; }

#pragma unroll
        for (int d = 0; d < DD; d++) {
            const ulonglong2 xA = *(const ulonglong2*)(xp + d * BT);
            const ulonglong2 xB = *(const ulonglong2*)(xp + d * BT + 4);
            const u64 xv[4] = {xA.x, xA.y, xB.x, xB.y};

            const u64 aa0 = bcast2(wa2[d].x);
            const u64 aa1 = bcast2(wa2[d].y);
            const u64 bb0 = bcast2(wb2[d].x);
            const u64 bb1 = bcast2(wb2[d].y);
#pragma unroll
            for (int p = 0; p < 4; p++) {
                const u64 z0 = ffma2(xv[p], aa0, bb0);
                acc0[p] = ffma2(z0, z0, acc0[p]);
                const u64 z1 = ffma2(xv[p], aa1, bb1);
                acc1[p] = ffma2(z1, z1, acc1[p]);
            }
        }

        // ---- Epilogue: out[b][r][k0..k0+1] = -0.5*acc + C ----
        const int b0 = t * BT;
        const u64 nh  = bcast2(-0.5f);
        const u64 cc0 = bcast2(c2.x);
        const u64 cc1 = bcast2(c2.y);
#pragma unroll
        for (int p = 0; p < 4; p++) {
            const u64 o0 = ffma2(acc0[p], nh, cc0);
            const u64 o1 = ffma2(acc1[p], nh, cc1);
            float o0lo, o0hi, o1lo, o1hi;
            unpack2(o0, o0lo, o0hi);
            unpack2(o1, o1lo, o1hi);
            *(float2*)&out[((size_t)(b0 + 2 * p)     * RR + r) * KK + k0] =
                make_float2(o0lo, o1lo);
            *(float2*)&out[((size_t)(b0 + 2 * p + 1) * RR + r) * KK + k0] =
                make_float2(o0hi, o1hi);
        }
    }
}

// ---------------------------------------------------------------------------
#define SMEM_BYTES ((2 * BT * XPITCH + RG * GPITCH) * 4 + RG * DD * 4)

extern "C" void kernel_launch(void* const* d_in, const int* in_sizes, int n_in,
                              void* d_out, int out_size) {
    const float* x       = (const float*)d_in[0];
    const void*  regions = d_in[1];                // int64 or int32, detected
    const float* means   = (const float*)d_in[2];
    const float* scales  = (const float*)d_in[3];
    float*       out     = (float*)d_out;

    cudaFuncSetAttribute(main_kernel,
                         cudaFuncAttributeMaxDynamicSharedMemorySize,
                         SMEM_BYTES);

    prep_kernel<<<RR, 512>>>(means, scales, regions);

    dim3 grid(GRIDX, RR / RG);
    main_kernel<<<grid, THREADS, SMEM_BYTES>>>(x, out);
}